// round 17
// baseline (speedup 1.0000x reference)
#include <cuda_runtime.h>
#include <cuda_fp16.h>
#include <cstdint>
#include <cstddef>

// ============================================================================
// Conductor: 2-layer LSTM (B=1024, H=1024, 4 steps, const input z) + Linear.
// sm_100 legacy mma.sync path.
//
// Round 17 = R16 fp16 kernel (measured 518.4us, best) with one change:
// mainloop load-issue order moved to barrier->load(t+2)->compute(t)
// (R12's measured-faster ordering) so cp.async latency overlaps the full
// MMA phase. Everything else identical:
//   fp16 m16n8k16, K-tile 64, CTA 128x128, 8 warps 64x32, 256 thr,
//   3-stage cp.async, 2 CTA/SM, fused LSTM cell epilogue (smem staging),
//   gate-interleaved fp16 weights, c/G0x/bias/acc/output fp32.
// ============================================================================

#define B_   1024
#define H_   1024
#define H4_  4096
#define KDIM 1024

#define NS 3
#define STAGE_F 8192                   // floats of smem per stage (A 16KB + B 16KB)
#define SMEM_TOTAL (NS * STAGE_F * 4)  // 98304 bytes

// ---------------- device scratch (static; no runtime allocation) ------------
__device__ __half g_h0[2][B_ * H_];
__device__ __half g_h1[2][B_ * H_];
__device__ float  g_c0[B_ * H_];
__device__ float  g_c1[B_ * H_];
__device__ float  g_G0x[(size_t)B_ * H4_];
__device__ __half g_hist[(size_t)B_ * 4 * H_];                   // [b][step][h]
__device__ __half g_Wr[(size_t)4 * H4_ * H_ + (size_t)H_ * H_];  // fp16 weights
__device__ float  g_bs0[H4_];   // permuted b_ih0+b_hh0
__device__ float  g_bs1[H4_];   // permuted b_ih1+b_hh1

// ---------------- helpers ----------------------------------------------------
__device__ __forceinline__ void cp16(void* sm, const void* gm) {
    uint32_t s = (uint32_t)__cvta_generic_to_shared(sm);
    asm volatile("cp.async.cg.shared.global [%0], [%1], 16;" :: "r"(s), "l"(gm) : "memory");
}

// fp16 MMA: D(fp32) += A(fp16) * B(fp16); A 4 regs, B 2 regs, K=16.
__device__ __forceinline__ void mma16(float* d, const uint32_t* a, const uint32_t* b) {
    asm volatile(
        "mma.sync.aligned.m16n8k16.row.col.f32.f16.f16.f32 "
        "{%0,%1,%2,%3},{%4,%5,%6,%7},{%8,%9},{%0,%1,%2,%3};"
        : "+f"(d[0]), "+f"(d[1]), "+f"(d[2]), "+f"(d[3])
        : "r"(a[0]), "r"(a[1]), "r"(a[2]), "r"(a[3]), "r"(b[0]), "r"(b[1]));
}

__device__ __forceinline__ int swz(int row, int grp) {
    // rows of 128B (32 "float" slots = 64 fp16); 8 16B groups, XOR swizzle
    return row * 32 + (((grp) ^ (row & 7)) << 2);
}

__device__ __forceinline__ float sigmf(float x) { return 1.f / (1.f + __expf(-x)); }

// ---------------- weight conversion + gate-interleave permutation -----------
// LSTM weights: dst row 4j+g = src row g*1024+j (gate order i,f,g,o). W_lin: id.
struct RoundArgs {
    const float4* src[5];
    __half*       dst[5];
};

__global__ void round_all_kernel(RoundArgs a) {
    int i = blockIdx.x * blockDim.x + threadIdx.x;
    const int WSEG = (H4_ * H_) / 4;        // 1M float4 per LSTM matrix
    int seg;
    size_t soff, doff;
    if (i < 4 * WSEG) {
        seg = i / WSEG;
        int off = i % WSEG;
        int rp = off >> 8;                  // dst row (256 float4/row)
        int c4 = off & 255;
        int j = rp >> 2, g = rp & 3;
        soff = (size_t)(g * 1024 + j) * 256 + c4;
        doff = off;
    } else {
        seg = 4;
        int off = i - 4 * WSEG;
        if (off >= (H_ * H_) / 4) return;
        soff = doff = off;
    }
    float4 v = a.src[seg][soff];
    __half2* d2 = (__half2*)(a.dst[seg] + doff * 4);
    d2[0] = __floats2half2_rn(v.x, v.y);
    d2[1] = __floats2half2_rn(v.z, v.w);
}

__global__ void bias_perm_kernel(const float* __restrict__ bi0, const float* __restrict__ bh0,
                                 const float* __restrict__ bi1, const float* __restrict__ bh1,
                                 float* __restrict__ bs0, float* __restrict__ bs1) {
    int t = blockIdx.x * blockDim.x + threadIdx.x;   // 0..4095
    int j = t >> 2, g = t & 3;
    int s = g * 1024 + j;
    bs0[t] = bi0[s] + bh0[s];
    bs1[t] = bi1[s] + bh1[s];
}

__global__ void init_kernel(const float4* __restrict__ z4,
                            __half* __restrict__ h0, float4* __restrict__ c0,
                            __half* __restrict__ h1, float4* __restrict__ c1) {
    int i = blockIdx.x * blockDim.x + threadIdx.x;
    float4 v = z4[i];
    __half2 p0 = __floats2half2_rn(v.x, v.y);
    __half2 p1 = __floats2half2_rn(v.z, v.w);
    ((__half2*)(h0 + i * 4))[0] = p0; ((__half2*)(h0 + i * 4))[1] = p1;
    ((__half2*)(h1 + i * 4))[0] = p0; ((__half2*)(h1 + i * 4))[1] = p1;
    c0[i] = v;  c1[i] = v;
}

// ---------------- fused fp16 GEMM (+optional LSTM cell epilogue) -------------
// acc[M,N] = sum_pairs A@W^T (+bias)(+Cadd);  A:[M,1024] fp16 rm, W fp16 rm.
// CELL: gate-interleaved cols (4j+g); epilogue computes the cell, writes
// h_out (fp16), c_out (fp32), hist (fp16). Otherwise writes C (fp32).
// CTA 128x128, K-tiles of 64 fp16, 3-stage cp.async, 8 warps (64x32).
template <bool PAIR2, bool CADD, bool BIAS, bool CELL>
__global__ void __launch_bounds__(256, 2)
gemm_f(const __half* __restrict__ A1, const __half* __restrict__ W1,
       const __half* __restrict__ A2, const __half* __restrict__ W2,
       const float* __restrict__ Cadd, const float* __restrict__ bias,
       float* __restrict__ C, int ldc,
       const float* __restrict__ c_in, float* __restrict__ c_out,
       __half* __restrict__ h_out, __half* __restrict__ hist, int step) {
    extern __shared__ float sm[];   // NS * 8192 floats

    const int tid  = threadIdx.x;
    const int lane = tid & 31;
    const int warp = tid >> 5;
    const int wm   = (warp & 1) * 64;
    const int wn   = (warp >> 1) * 32;
    const int mBase = blockIdx.y * 128;
    const int nBase = blockIdx.x * 128;

    const __half* Ae1 = A1 + (size_t)mBase * KDIM;
    const __half* We1 = W1 + (size_t)nBase * KDIM;
    const __half* Ae2 = PAIR2 ? A2 + (size_t)mBase * KDIM : nullptr;
    const __half* We2 = PAIR2 ? W2 + (size_t)nBase * KDIM : nullptr;

    const int g    = tid & 7;
    const int rowb = tid >> 3;
    int soff[4];
#pragma unroll
    for (int i = 0; i < 4; i++) soff[i] = swz(rowb + i * 32, g);

    float acc[4][4][4];
#pragma unroll
    for (int mi = 0; mi < 4; mi++)
#pragma unroll
        for (int ni = 0; ni < 4; ni++)
#pragma unroll
            for (int k = 0; k < 4; k++) acc[mi][ni][k] = 0.f;

    const int T = PAIR2 ? 32 : 16;          // K-tiles of 64 fp16

    auto load_tile = [&](int tt) {
        const __half* Ap = (!PAIR2 || tt < 16) ? Ae1 : Ae2;
        const __half* Wp = (!PAIR2 || tt < 16) ? We1 : We2;
        const int k0 = (tt & 15) * 64 + g * 8;       // fp16 elements
        float* As = sm + (tt % NS) * STAGE_F;
        float* Bs = As + 4096;
#pragma unroll
        for (int i = 0; i < 4; i++) {
            int r = rowb + i * 32;
            cp16(As + soff[i], Ap + (size_t)r * KDIM + k0);
            cp16(Bs + soff[i], Wp + (size_t)r * KDIM + k0);
        }
        asm volatile("cp.async.commit_group;" ::: "memory");
    };

    load_tile(0);
    load_tile(1);

    const int fr = lane >> 2, fc = lane & 3;

    for (int t = 0; t < T; ++t) {
        asm volatile("cp.async.wait_group 1;" ::: "memory");
        __syncthreads();                     // all warps done reading stage (t-1)%NS

        if (t + 2 < T) load_tile(t + 2);     // issue next load BEFORE compute
        else           asm volatile("cp.async.commit_group;" ::: "memory");

        const float* As = sm + (t % NS) * STAGE_F;
        const float* Bs = As + 4096;
#pragma unroll
        for (int ks = 0; ks < 4; ++ks) {             // 4 x K=16 per 64-elem tile
            const int g0 = ks * 2, g1 = g0 + 1;
            uint32_t af[4][4];
#pragma unroll
            for (int mi = 0; mi < 4; mi++) {
                int r0 = wm + mi * 16 + fr;
                int r1 = r0 + 8;
                af[mi][0] = __float_as_uint(As[swz(r0, g0) + fc]);
                af[mi][1] = __float_as_uint(As[swz(r1, g0) + fc]);
                af[mi][2] = __float_as_uint(As[swz(r0, g1) + fc]);
                af[mi][3] = __float_as_uint(As[swz(r1, g1) + fc]);
            }
            uint32_t bf[4][2];
#pragma unroll
            for (int ni = 0; ni < 4; ni++) {
                int rn = wn + ni * 8 + fr;
                bf[ni][0] = __float_as_uint(Bs[swz(rn, g0) + fc]);
                bf[ni][1] = __float_as_uint(Bs[swz(rn, g1) + fc]);
            }
#pragma unroll
            for (int mi = 0; mi < 4; mi++)
#pragma unroll
                for (int ni = 0; ni < 4; ni++)
                    mma16(acc[mi][ni], af[mi], bf[ni]);
        }
    }

    // ---- epilogue ----
    const int er = lane >> 2, ec = (lane & 3) * 2;

    if (!CELL) {
#pragma unroll
        for (int mi = 0; mi < 4; mi++) {
#pragma unroll
            for (int ni = 0; ni < 4; ni++) {
                const int row0 = mBase + wm + mi * 16 + er;
                const int col  = nBase + wn + ni * 8 + ec;
                float b0 = 0.f, b1 = 0.f;
                if (BIAS) { b0 = bias[col]; b1 = bias[col + 1]; }
                float2 o0 = make_float2(acc[mi][ni][0] + b0, acc[mi][ni][1] + b1);
                float2 o1 = make_float2(acc[mi][ni][2] + b0, acc[mi][ni][3] + b1);
                if (CADD) {
                    float2 a0 = *(const float2*)(Cadd + (size_t)row0 * ldc + col);
                    float2 a1 = *(const float2*)(Cadd + (size_t)(row0 + 8) * ldc + col);
                    o0.x += a0.x; o0.y += a0.y; o1.x += a1.x; o1.y += a1.y;
                }
                *(float2*)(C + (size_t)row0 * ldc + col)       = o0;
                *(float2*)(C + (size_t)(row0 + 8) * ldc + col) = o1;
            }
        }
        return;
    }

    // CELL epilogue: stage gates to smem (stride 132), then compute LSTM cell.
    __syncthreads();                     // pipeline smem -> staging reuse
    float* S = sm;                       // 128 x 132
#pragma unroll
    for (int mi = 0; mi < 4; mi++) {
#pragma unroll
        for (int ni = 0; ni < 4; ni++) {
            const int r0  = wm + mi * 16 + er;
            const int col = wn + ni * 8 + ec;
            float b0 = 0.f, b1 = 0.f;
            if (BIAS) { b0 = bias[nBase + col]; b1 = bias[nBase + col + 1]; }
            float v0 = acc[mi][ni][0] + b0, v1 = acc[mi][ni][1] + b1;
            float v2 = acc[mi][ni][2] + b0, v3 = acc[mi][ni][3] + b1;
            if (CADD) {
                const int gr0 = mBase + r0;
                float2 a0 = *(const float2*)(Cadd + (size_t)gr0 * ldc + nBase + col);
                float2 a1 = *(const float2*)(Cadd + (size_t)(gr0 + 8) * ldc + nBase + col);
                v0 += a0.x; v1 += a0.y; v2 += a1.x; v3 += a1.y;
            }
            S[r0 * 132 + col]           = v0;
            S[r0 * 132 + col + 1]       = v1;
            S[(r0 + 8) * 132 + col]     = v2;
            S[(r0 + 8) * 132 + col + 1] = v3;
        }
    }
    __syncthreads();

    const int mg = tid >> 3;             // 0..31 -> rows 4mg..4mg+3
    const int jg = tid & 7;              // 0..7  -> local j units jg*4..+3
    const int j0 = (nBase >> 2) + jg * 4;
#pragma unroll
    for (int r = 0; r < 4; ++r) {
        const int row = mg * 4 + r;
        const int m   = mBase + row;
        const float4* gp = (const float4*)&S[row * 132 + jg * 16];
        float4 q0 = gp[0], q1 = gp[1], q2 = gp[2], q3 = gp[3];
        float4 cin = *(const float4*)&c_in[(size_t)m * H_ + j0];

        float4 cc, hh;
        cc.x = sigmf(q0.y) * cin.x + sigmf(q0.x) * tanhf(q0.z);
        cc.y = sigmf(q1.y) * cin.y + sigmf(q1.x) * tanhf(q1.z);
        cc.z = sigmf(q2.y) * cin.z + sigmf(q2.x) * tanhf(q2.z);
        cc.w = sigmf(q3.y) * cin.w + sigmf(q3.x) * tanhf(q3.z);
        hh.x = sigmf(q0.w) * tanhf(cc.x);
        hh.y = sigmf(q1.w) * tanhf(cc.y);
        hh.z = sigmf(q2.w) * tanhf(cc.z);
        hh.w = sigmf(q3.w) * tanhf(cc.w);

        *(float4*)&c_out[(size_t)m * H_ + j0] = cc;
        __half2 p0 = __floats2half2_rn(hh.x, hh.y);
        __half2 p1 = __floats2half2_rn(hh.z, hh.w);
        __half2* hp = (__half2*)(h_out + (size_t)m * H_ + j0);
        hp[0] = p0; hp[1] = p1;
        if (hist) {
            __half2* tp = (__half2*)(hist + ((size_t)m * 4 + step) * H_ + j0);
            tp[0] = p0; tp[1] = p1;
        }
    }
}

// ---------------- host launcher ---------------------------------------------
extern "C" void kernel_launch(void* const* d_in, const int* in_sizes, int n_in,
                              void* d_out, int out_size) {
    const float* z     = (const float*)d_in[0];
    const float* W_ih0 = (const float*)d_in[1];
    const float* W_hh0 = (const float*)d_in[2];
    const float* b_ih0 = (const float*)d_in[3];
    const float* b_hh0 = (const float*)d_in[4];
    const float* W_ih1 = (const float*)d_in[5];
    const float* W_hh1 = (const float*)d_in[6];
    const float* b_ih1 = (const float*)d_in[7];
    const float* b_hh1 = (const float*)d_in[8];
    const float* W_lin = (const float*)d_in[9];
    const float* b_lin = (const float*)d_in[10];

    __half *h0, *h1, *hist, *Wr;
    float *c0, *c1, *G0x, *bs0, *bs1;
    cudaGetSymbolAddress((void**)&h0,   g_h0);
    cudaGetSymbolAddress((void**)&h1,   g_h1);
    cudaGetSymbolAddress((void**)&c0,   g_c0);
    cudaGetSymbolAddress((void**)&c1,   g_c1);
    cudaGetSymbolAddress((void**)&G0x,  g_G0x);
    cudaGetSymbolAddress((void**)&hist, g_hist);
    cudaGetSymbolAddress((void**)&Wr,   g_Wr);
    cudaGetSymbolAddress((void**)&bs0,  g_bs0);
    cudaGetSymbolAddress((void**)&bs1,  g_bs1);

    __half* h0b[2] = {h0, h0 + (size_t)B_ * H_};
    __half* h1b[2] = {h1, h1 + (size_t)B_ * H_};

    __half* Wih0p = Wr;
    __half* Whh0p = Wr + (size_t)4 * 1024 * 1024;
    __half* Wih1p = Wr + (size_t)8 * 1024 * 1024;
    __half* Whh1p = Wr + (size_t)12 * 1024 * 1024;
    __half* Wlinr = Wr + (size_t)16 * 1024 * 1024;

    cudaFuncSetAttribute((const void*)gemm_f<false, false, true, false>,
                         cudaFuncAttributeMaxDynamicSharedMemorySize, SMEM_TOTAL);
    cudaFuncSetAttribute((const void*)gemm_f<false, true, false, true>,
                         cudaFuncAttributeMaxDynamicSharedMemorySize, SMEM_TOTAL);
    cudaFuncSetAttribute((const void*)gemm_f<true, false, true, true>,
                         cudaFuncAttributeMaxDynamicSharedMemorySize, SMEM_TOTAL);

    // 1) convert + permute weights to fp16; permuted summed biases; init state
    {
        RoundArgs ra;
        ra.src[0] = (const float4*)W_ih0; ra.dst[0] = Wih0p;
        ra.src[1] = (const float4*)W_hh0; ra.dst[1] = Whh0p;
        ra.src[2] = (const float4*)W_ih1; ra.dst[2] = Wih1p;
        ra.src[3] = (const float4*)W_hh1; ra.dst[3] = Whh1p;
        ra.src[4] = (const float4*)W_lin; ra.dst[4] = Wlinr;
        const int total4 = 4 * (H4_ * H_) / 4 + (H_ * H_) / 4;
        round_all_kernel<<<(total4 + 255) / 256, 256>>>(ra);
    }
    bias_perm_kernel<<<H4_ / 256, 256>>>(b_ih0, b_hh0, b_ih1, b_hh1, bs0, bs1);
    init_kernel<<<(B_ * H_ / 4) / 256, 256>>>((const float4*)z, h0b[0], (float4*)c0,
                                              h1b[0], (float4*)c1);

    // 2) G0x = fp16(z) @ W_ih0p^T + bs0   (permuted gate layout, fp32 out)
    dim3 gBig(H4_ / 128, B_ / 128);    // (32, 8) -> 256 CTAs, 2/SM, single wave
    gemm_f<false, false, true, false><<<gBig, 256, SMEM_TOTAL>>>(
        h0b[0], Wih0p, nullptr, nullptr, nullptr, bs0, G0x, H4_,
        nullptr, nullptr, nullptr, nullptr, 0);

    // 3) recurrence: 2 fused GEMM+cell launches per step
    for (int s = 0; s < 4; ++s) {
        const int in = s & 1, out = in ^ 1;
        // layer0: gates = h0 @ W_hh0p^T + G0x -> cell -> h0', c0
        gemm_f<false, true, false, true><<<gBig, 256, SMEM_TOTAL>>>(
            h0b[in], Whh0p, nullptr, nullptr, G0x, nullptr, nullptr, H4_,
            c0, c0, h0b[out], nullptr, s);
        // layer1: gates = h0' @ W_ih1p^T + h1 @ W_hh1p^T + bs1 -> cell -> h1', c1, hist
        gemm_f<true, false, true, true><<<gBig, 256, SMEM_TOTAL>>>(
            h0b[out], Wih1p, h1b[in], Whh1p, nullptr, bs1, nullptr, H4_,
            c1, c1, h1b[out], hist, s);
    }

    // 4) out = hist @ W_lin^T + b_lin   (single M=4096 GEMM, fp32 output)
    dim3 gOut(H_ / 128, (B_ * 4) / 128);  // (8, 32)
    gemm_f<false, false, true, false><<<gOut, 256, SMEM_TOTAL>>>(
        hist, Wlinr, nullptr, nullptr, nullptr, b_lin, (float*)d_out, H_,
        nullptr, nullptr, nullptr, nullptr, 0);
}